// round 12
// baseline (speedup 1.0000x reference)
#include <cuda_runtime.h>
#include <cstdint>
#include <math.h>

#define HID    1024
#define MTOT   16384      // 4 * 4096 tokens
#define NHEAD  16
#define HDIM   64

// ---------------------------------------------------------------------------
// Scratch (device globals; allocation-free per harness rules)
// ---------------------------------------------------------------------------
__device__ float g_xa[MTOT * HID];        // x converted to tf32 (rna)
__device__ float g_wt[4][HID * HID];      // Wq,Wk,Wv,Wo transposed + tf32(rna)
__device__ float g_q[MTOT * HID];
__device__ float g_k[MTOT * HID];
__device__ float g_v[MTOT * HID];
__device__ float g_attn[MTOT * HID];      // attention out, tf32(rna)

// ---------------------------------------------------------------------------
// Helpers (portable PTX only: no 'a'-gated instructions)
// ---------------------------------------------------------------------------
__device__ __forceinline__ float to_tf32(float x) {
    float r;
    asm("cvt.rna.tf32.f32 %0, %1;" : "=f"(r) : "f"(x));
    return r;
}
__device__ __forceinline__ void cp_async16(uint32_t dst, const void* src) {
    asm volatile("cp.async.cg.shared.global [%0], [%1], 16;" :: "r"(dst), "l"(src));
}
#define CP_COMMIT()   asm volatile("cp.async.commit_group;" ::: "memory")
#define CP_WAIT(n)    asm volatile("cp.async.wait_group %0;" :: "n"(n) : "memory")

__device__ __forceinline__ uint32_t smem_u32(const void* p) {
    uint32_t a;
    asm("{ .reg .u64 t; cvta.to.shared.u64 t, %1; cvt.u32.u64 %0, t; }"
        : "=r"(a) : "l"(p));
    return a;
}

__device__ __forceinline__ void mma_tf32(float c[4],
                                         uint32_t a0, uint32_t a1,
                                         uint32_t a2, uint32_t a3,
                                         uint32_t b0, uint32_t b1) {
    asm volatile(
        "mma.sync.aligned.m16n8k8.row.col.f32.tf32.tf32.f32 "
        "{%0,%1,%2,%3}, {%4,%5,%6,%7}, {%8,%9}, {%0,%1,%2,%3};"
        : "+f"(c[0]), "+f"(c[1]), "+f"(c[2]), "+f"(c[3])
        : "r"(a0), "r"(a1), "r"(a2), "r"(a3), "r"(b0), "r"(b1));
}

__device__ __forceinline__ void ldsm_x4(uint32_t& r0, uint32_t& r1,
                                        uint32_t& r2, uint32_t& r3,
                                        uint32_t addr) {
    asm volatile("ldmatrix.sync.aligned.m8n8.x4.shared.b16 {%0,%1,%2,%3}, [%4];"
                 : "=r"(r0), "=r"(r1), "=r"(r2), "=r"(r3) : "r"(addr));
}

// ---------------------------------------------------------------------------
// Staging (single launch): flat grid.
//   blocks [0, NCONV)            : tf32-round x (float4 per thread)
//   blocks [NCONV, NCONV+NTRAN)  : transpose+round the 4 weight matrices
// ---------------------------------------------------------------------------
#define NCONV (MTOT * HID / 4 / 256)            // 16384 blocks
#define NTPW  ((HID / 32) * (HID / 32))         // 1024 tiles per W
#define NTRAN (4 * NTPW)                        // 4096 blocks

__global__ __launch_bounds__(256)
void staging_kernel(const float* __restrict__ x, float* __restrict__ xa,
                    const float* __restrict__ W0, const float* __restrict__ W1,
                    const float* __restrict__ W2, const float* __restrict__ W3,
                    float* __restrict__ T) {
    if (blockIdx.x < NCONV) {
        int i = blockIdx.x * 256 + threadIdx.x;  // float4 index
        float4 v = reinterpret_cast<const float4*>(x)[i];
        v.x = to_tf32(v.x); v.y = to_tf32(v.y);
        v.z = to_tf32(v.z); v.w = to_tf32(v.w);
        reinterpret_cast<float4*>(xa)[i] = v;
        return;
    }
    __shared__ float tile[32][33];
    const int b  = blockIdx.x - NCONV;
    const int wz = b / NTPW;                 // which W
    const int tz = b % NTPW;
    const int bx = tz & 31, by = tz >> 5;    // 32x32 tile coords
    const float* __restrict__ W =
        (wz == 0) ? W0 : (wz == 1) ? W1 : (wz == 2) ? W2 : W3;
    float* __restrict__ Tm = T + (size_t)wz * HID * HID;

    int tx = threadIdx.x & 31, ty = threadIdx.x >> 5;  // 32x8
    int x0 = bx * 32, y0 = by * 32;
#pragma unroll
    for (int j = 0; j < 4; j++)
        tile[ty + j * 8][tx] = W[(size_t)(y0 + ty + j * 8) * HID + x0 + tx];
    __syncthreads();
#pragma unroll
    for (int j = 0; j < 4; j++)
        Tm[(size_t)(x0 + ty + j * 8) * HID + y0 + tx] = to_tf32(tile[tx][ty + j * 8]);
}

// ---------------------------------------------------------------------------
// mma.sync tf32 GEMM: C[M,N] = A[M,K] @ Bt[N,K]^T + bias
// CTA 128x128, BK=16, 4-stage cp.async, 4 warps (2x2), 64x64 warp tiles.
// R12: within-iteration pipelining ONLY — both k8 fragment blocks loaded
// right after the barrier (k8=1's LDSM latency hides under k8=0's MMAs);
// next-stage cp.async issued between the two MMA halves. Nothing crosses
// any __syncthreads; stage-ring semantics identical to the proven R10.
// ---------------------------------------------------------------------------
#define BM 128
#define BN 128
#define BK 16
#define RS 20                      // padded row stride (floats)
#define STAGES 4
#define TILE_FLOATS (BM * RS)      // 2560 per operand per stage
#define GSMEM (STAGES * 2 * TILE_FLOATS * 4)   // 81920 bytes
#define GTHREADS 128

__global__ __launch_bounds__(GTHREADS, 2)
void gemm_tf32_kernel(const float* __restrict__ A,
                      const float* __restrict__ Bt0, const float* __restrict__ Bt1,
                      const float* __restrict__ Bt2,
                      const float* __restrict__ b0, const float* __restrict__ b1,
                      const float* __restrict__ b2,
                      float* __restrict__ C0, float* __restrict__ C1,
                      float* __restrict__ C2)
{
    extern __shared__ float smf[];   // [As stages | Bs stages]
    const uint32_t sbase = smem_u32(smf);
    const uint32_t breg  = (uint32_t)(STAGES * TILE_FLOATS) * 4;

    const int z = blockIdx.z;
    const float* __restrict__ Bt   = (z == 0) ? Bt0 : (z == 1) ? Bt1 : Bt2;
    const float* __restrict__ bias = (z == 0) ? b0 : (z == 1) ? b1 : b2;
    float*       __restrict__ C    = (z == 0) ? C0 : (z == 1) ? C1 : C2;

    const int tid  = threadIdx.x;
    const int wid  = tid >> 5;
    const int lane = tid & 31;
    const int wm   = wid >> 1;        // 0..1 -> M offset 64*wm
    const int wn   = wid & 1;         // 0..1 -> N offset 64*wn
    const int lg   = lane >> 2;       // 0..7
    const int lr   = lane & 3;        // 0..3

    const int m0 = blockIdx.y * BM;
    const int n0 = blockIdx.x * BN;

    float acc[4][8][4];
#pragma unroll
    for (int i = 0; i < 4; i++)
#pragma unroll
        for (int j = 0; j < 8; j++)
#pragma unroll
            for (int q = 0; q < 4; q++) acc[i][j][q] = 0.f;

    const int sel = lane >> 3;
    const int lr8 = lane & 7;
    uint32_t aoff[4];
#pragma unroll
    for (int i = 0; i < 4; i++) {
        int row = wm * 64 + i * 16 + ((sel & 1) ? 8 : 0) + lr8;
        int col = (sel >> 1) * 4;
        aoff[i] = (uint32_t)(row * RS + col) * 4;
    }
    uint32_t boff[4];
#pragma unroll
    for (int jp = 0; jp < 4; jp++) {
        int row = wn * 64 + jp * 16 + ((sel >> 1) ? 8 : 0) + lr8;
        int col = (sel & 1) * 4;
        boff[jp] = breg + (uint32_t)(row * RS + col) * 4;
    }

    const int grow0 = tid >> 2;            // rows 0..31 (then +32,+64,+96)
    const int gk    = (tid & 3) << 2;      // k offset 0,4,8,12
    const uint32_t dstA0 = sbase + (uint32_t)(grow0 * RS + gk) * 4;
    const uint32_t dstB0 = sbase + breg + (uint32_t)(grow0 * RS + gk) * 4;
    const uint32_t rowstep = (uint32_t)(32 * RS) * 4;   // +32 rows

    auto load_stage = [&](int s, int k0) {
        const uint32_t soff = (uint32_t)(s * TILE_FLOATS) * 4;
        const float* Ap = A  + (size_t)(m0 + grow0) * HID + k0 + gk;
        const float* Bp = Bt + (size_t)(n0 + grow0) * HID + k0 + gk;
#pragma unroll
        for (int r = 0; r < 4; r++)
            cp_async16(dstA0 + soff + r * rowstep, Ap + (size_t)(r * 32) * HID);
#pragma unroll
        for (int r = 0; r < 4; r++)
            cp_async16(dstB0 + soff + r * rowstep, Bp + (size_t)(r * 32) * HID);
        CP_COMMIT();
    };

    // register fragment buffers for both k8 blocks of the current stage
    uint32_t afb[2][4][4], bfb[2][8][2];

    auto load_frags = [&](int buf, uint32_t kb) {
#pragma unroll
        for (int i = 0; i < 4; i++)
            ldsm_x4(afb[buf][i][0], afb[buf][i][1],
                    afb[buf][i][2], afb[buf][i][3], kb + aoff[i]);
#pragma unroll
        for (int jp = 0; jp < 4; jp++)
            ldsm_x4(bfb[buf][jp * 2][0], bfb[buf][jp * 2][1],
                    bfb[buf][jp * 2 + 1][0], bfb[buf][jp * 2 + 1][1],
                    kb + boff[jp]);
    };
    auto mma_all = [&](int buf) {
#pragma unroll
        for (int i = 0; i < 4; i++)
#pragma unroll
            for (int j = 0; j < 8; j++)
                mma_tf32(acc[i][j],
                         afb[buf][i][0], afb[buf][i][1],
                         afb[buf][i][2], afb[buf][i][3],
                         bfb[buf][j][0], bfb[buf][j][1]);
    };

#pragma unroll
    for (int s = 0; s < STAGES - 1; s++) load_stage(s, s * BK);

    const int KIT = HID / BK;   // 64
#pragma unroll 1
    for (int it = 0; it < KIT; it++) {
        CP_WAIT(STAGES - 2);
        __syncthreads();

        const int s = it % STAGES;
        const uint32_t soff = sbase + (uint32_t)(s * TILE_FLOATS) * 4;

        // load BOTH k8 fragment blocks up front (k8=1 latency hides under
        // the k8=0 MMA stream)
        load_frags(0, soff);
        load_frags(1, soff + 32);

        mma_all(0);

        // next-stage global prefetch between the MMA halves: LDGSTS drains
        // on the LSU while 32 MMAs are still queued on the tensor pipe.
        const int jn = it + STAGES - 1;
        if (jn < KIT) load_stage(jn % STAGES, jn * BK);

        mma_all(1);
    }

#pragma unroll
    for (int i = 0; i < 4; i++) {
        const int row = m0 + wm * 64 + i * 16 + lg;
#pragma unroll
        for (int j = 0; j < 8; j++) {
            const int col = n0 + wn * 64 + j * 8 + lr * 2;
            const float bx = bias[col], by = bias[col + 1];
            float2 v0 = make_float2(acc[i][j][0] + bx, acc[i][j][1] + by);
            float2 v1 = make_float2(acc[i][j][2] + bx, acc[i][j][3] + by);
            *reinterpret_cast<float2*>(&C[(size_t)row * HID + col])       = v0;
            *reinterpret_cast<float2*>(&C[(size_t)(row + 8) * HID + col]) = v1;
        }
    }
}

// ---------------------------------------------------------------------------
// Per-token head-to-head attention: TWO tokens per 256-thread block (R10).
// ---------------------------------------------------------------------------
#define KTS 17   // skT4 row stride (float4)

__global__ __launch_bounds__(256)
void attention_kernel(const float* __restrict__ q,
                      const float* __restrict__ k,
                      const float* __restrict__ v,
                      float* __restrict__ attn)
{
    __shared__ float4 sq4[2][NHEAD * 16];     // [tok][h][d4]
    __shared__ float4 skT4[2][16 * KTS];      // [tok][d4][e]
    __shared__ float4 sv4[2][NHEAD * 16];     // [tok][e][d4]

    const int t  = threadIdx.x;
    const int hi = t >> 4;      // head
    const int lo = t & 15;      // score: e, output: d4
    const size_t b0 = (size_t)(blockIdx.x * 2) * (HID / 4);
    const size_t b1 = b0 + (HID / 4);

    const float4* q4 = reinterpret_cast<const float4*>(q);
    const float4* k4 = reinterpret_cast<const float4*>(k);
    const float4* v4 = reinterpret_cast<const float4*>(v);

    float4 q0 = q4[b0 + t], k0 = k4[b0 + t], v0 = v4[b0 + t];
    float4 q1 = q4[b1 + t], k1 = k4[b1 + t], v1 = v4[b1 + t];

    sq4[0][t]              = q0;
    skT4[0][lo * KTS + hi] = k0;
    sv4[0][t]              = v0;
    sq4[1][t]              = q1;
    skT4[1][lo * KTS + hi] = k1;
    sv4[1][t]              = v1;
    __syncthreads();

    const int lanebase = t & 16;
#pragma unroll
    for (int tok = 0; tok < 2; tok++) {
        float s = 0.f;
#pragma unroll
        for (int i = 0; i < 16; i++) {
            float4 a = sq4[tok][hi * 16 + i];
            float4 b = skT4[tok][i * KTS + lo];
            s += a.x * b.x + a.y * b.y + a.z * b.z + a.w * b.w;
        }
        s *= 0.125f;   // 1/sqrt(64)

        float mx = s;
#pragma unroll
        for (int off = 8; off >= 1; off >>= 1)
            mx = fmaxf(mx, __shfl_xor_sync(0xffffffffu, mx, off));
        float p = __expf(s - mx);
        float sum = p;
#pragma unroll
        for (int off = 8; off >= 1; off >>= 1)
            sum += __shfl_xor_sync(0xffffffffu, sum, off);
        p *= (1.f / sum);

        float4 o = make_float4(0.f, 0.f, 0.f, 0.f);
#pragma unroll
        for (int e = 0; e < NHEAD; e++) {
            float  pe = __shfl_sync(0xffffffffu, p, lanebase | e, 32);
            float4 vv = sv4[tok][e * 16 + lo];
            o.x += pe * vv.x; o.y += pe * vv.y;
            o.z += pe * vv.z; o.w += pe * vv.w;
        }
        o.x = to_tf32(o.x); o.y = to_tf32(o.y);
        o.z = to_tf32(o.z); o.w = to_tf32(o.w);
        reinterpret_cast<float4*>(attn)[(tok == 0 ? b0 : b1) + t] = o;
    }
}

// ---------------------------------------------------------------------------
// Launch
// ---------------------------------------------------------------------------
extern "C" void kernel_launch(void* const* d_in, const int* in_sizes, int n_in,
                              void* d_out, int out_size)
{
    const float* x  = (const float*)d_in[0];
    const float* Wq = (const float*)d_in[1];
    const float* bq = (const float*)d_in[2];
    const float* Wk = (const float*)d_in[3];
    const float* bk = (const float*)d_in[4];
    const float* Wv = (const float*)d_in[5];
    const float* bv = (const float*)d_in[6];
    const float* Wo = (const float*)d_in[7];
    const float* bo = (const float*)d_in[8];
    float* out = (float*)d_out;

    float *xa, *wt, *qp, *kp, *vp, *ap;
    cudaGetSymbolAddress((void**)&xa, g_xa);
    cudaGetSymbolAddress((void**)&wt, g_wt);
    cudaGetSymbolAddress((void**)&qp, g_q);
    cudaGetSymbolAddress((void**)&kp, g_k);
    cudaGetSymbolAddress((void**)&vp, g_v);
    cudaGetSymbolAddress((void**)&ap, g_attn);

    static bool attr_set = false;
    if (!attr_set) {
        cudaFuncSetAttribute(gemm_tf32_kernel,
                             cudaFuncAttributeMaxDynamicSharedMemorySize, GSMEM);
        attr_set = true;
    }

    // 0) staging (one launch): tf32-round x; transpose+round the four W's
    staging_kernel<<<NCONV + NTRAN, 256>>>(x, xa, Wq, Wk, Wv, Wo, wt);

    // 1) fused QKV projections
    dim3 gridQKV(HID / BN, MTOT / BM, 3);
    gemm_tf32_kernel<<<gridQKV, GTHREADS, GSMEM>>>(
        xa, wt + 0 * (size_t)HID * HID, wt + 1 * (size_t)HID * HID,
        wt + 2 * (size_t)HID * HID, bq, bk, bv, qp, kp, vp);

    // 2) per-token attention (2 tokens per block)
    attention_kernel<<<MTOT / 2, 256>>>(qp, kp, vp, ap);

    // 3) output projection
    dim3 gridO(HID / BN, MTOT / BM, 1);
    gemm_tf32_kernel<<<gridO, GTHREADS, GSMEM>>>(
        ap, wt + 3 * (size_t)HID * HID, wt + 3 * (size_t)HID * HID,
        wt + 3 * (size_t)HID * HID, bo, bo, bo, out, out, out);
}

// round 13
// speedup vs baseline: 1.0510x; 1.0510x over previous
#include <cuda_runtime.h>
#include <cstdint>
#include <math.h>

#define HID    1024
#define MTOT   16384      // 4 * 4096 tokens
#define NHEAD  16
#define HDIM   64

// ---------------------------------------------------------------------------
// Scratch (device globals; allocation-free per harness rules)
// ---------------------------------------------------------------------------
__device__ float g_xa[MTOT * HID];        // x converted to tf32 (rna)
__device__ float g_wt[4][HID * HID];      // Wq,Wk,Wv,Wo transposed + tf32(rna)
__device__ float g_q[MTOT * HID];
__device__ float g_k[MTOT * HID];
__device__ float g_v[MTOT * HID];
__device__ float g_attn[MTOT * HID];      // attention out, tf32(rna)

// ---------------------------------------------------------------------------
// Helpers (portable PTX only: no 'a'-gated instructions)
// ---------------------------------------------------------------------------
__device__ __forceinline__ float to_tf32(float x) {
    float r;
    asm("cvt.rna.tf32.f32 %0, %1;" : "=f"(r) : "f"(x));
    return r;
}
__device__ __forceinline__ void cp_async16(uint32_t dst, const void* src) {
    asm volatile("cp.async.cg.shared.global [%0], [%1], 16;" :: "r"(dst), "l"(src));
}
#define CP_COMMIT()   asm volatile("cp.async.commit_group;" ::: "memory")
#define CP_WAIT(n)    asm volatile("cp.async.wait_group %0;" :: "n"(n) : "memory")

__device__ __forceinline__ uint32_t smem_u32(const void* p) {
    uint32_t a;
    asm("{ .reg .u64 t; cvta.to.shared.u64 t, %1; cvt.u32.u64 %0, t; }"
        : "=r"(a) : "l"(p));
    return a;
}

__device__ __forceinline__ void mma_tf32(float c[4],
                                         uint32_t a0, uint32_t a1,
                                         uint32_t a2, uint32_t a3,
                                         uint32_t b0, uint32_t b1) {
    asm volatile(
        "mma.sync.aligned.m16n8k8.row.col.f32.tf32.tf32.f32 "
        "{%0,%1,%2,%3}, {%4,%5,%6,%7}, {%8,%9}, {%0,%1,%2,%3};"
        : "+f"(c[0]), "+f"(c[1]), "+f"(c[2]), "+f"(c[3])
        : "r"(a0), "r"(a1), "r"(a2), "r"(a3), "r"(b0), "r"(b1));
}

__device__ __forceinline__ void ldsm_x4(uint32_t& r0, uint32_t& r1,
                                        uint32_t& r2, uint32_t& r3,
                                        uint32_t addr) {
    asm volatile("ldmatrix.sync.aligned.m8n8.x4.shared.b16 {%0,%1,%2,%3}, [%4];"
                 : "=r"(r0), "=r"(r1), "=r"(r2), "=r"(r3) : "r"(addr));
}

// packed f32x2 helpers (exact fp32 FMA at 2x issue density)
__device__ __forceinline__ unsigned long long pack2(float lo, float hi) {
    unsigned long long r;
    asm("mov.b64 %0, {%1, %2};" : "=l"(r) : "f"(lo), "f"(hi));
    return r;
}
__device__ __forceinline__ void unpack2(unsigned long long v, float& lo, float& hi) {
    asm("mov.b64 {%0, %1}, %2;" : "=f"(lo), "=f"(hi) : "l"(v));
}
__device__ __forceinline__ unsigned long long fma2(unsigned long long a,
                                                   unsigned long long b,
                                                   unsigned long long c) {
    unsigned long long d;
    asm("fma.rn.f32x2 %0, %1, %2, %3;" : "=l"(d) : "l"(a), "l"(b), "l"(c));
    return d;
}

// ---------------------------------------------------------------------------
// Staging (single launch): flat grid.
// ---------------------------------------------------------------------------
#define NCONV (MTOT * HID / 4 / 256)            // 16384 blocks
#define NTPW  ((HID / 32) * (HID / 32))         // 1024 tiles per W
#define NTRAN (4 * NTPW)                        // 4096 blocks

__global__ __launch_bounds__(256)
void staging_kernel(const float* __restrict__ x, float* __restrict__ xa,
                    const float* __restrict__ W0, const float* __restrict__ W1,
                    const float* __restrict__ W2, const float* __restrict__ W3,
                    float* __restrict__ T) {
    if (blockIdx.x < NCONV) {
        int i = blockIdx.x * 256 + threadIdx.x;  // float4 index
        float4 v = reinterpret_cast<const float4*>(x)[i];
        v.x = to_tf32(v.x); v.y = to_tf32(v.y);
        v.z = to_tf32(v.z); v.w = to_tf32(v.w);
        reinterpret_cast<float4*>(xa)[i] = v;
        return;
    }
    __shared__ float tile[32][33];
    const int b  = blockIdx.x - NCONV;
    const int wz = b / NTPW;                 // which W
    const int tz = b % NTPW;
    const int bx = tz & 31, by = tz >> 5;    // 32x32 tile coords
    const float* __restrict__ W =
        (wz == 0) ? W0 : (wz == 1) ? W1 : (wz == 2) ? W2 : W3;
    float* __restrict__ Tm = T + (size_t)wz * HID * HID;

    int tx = threadIdx.x & 31, ty = threadIdx.x >> 5;  // 32x8
    int x0 = bx * 32, y0 = by * 32;
#pragma unroll
    for (int j = 0; j < 4; j++)
        tile[ty + j * 8][tx] = W[(size_t)(y0 + ty + j * 8) * HID + x0 + tx];
    __syncthreads();
#pragma unroll
    for (int j = 0; j < 4; j++)
        Tm[(size_t)(x0 + ty + j * 8) * HID + y0 + tx] = to_tf32(tile[tx][ty + j * 8]);
}

// ---------------------------------------------------------------------------
// mma.sync tf32 GEMM: C[M,N] = A[M,K] @ Bt[N,K]^T + bias
// CTA 128x128, BK=16 k-tiles in a FIVE-slot ring, consumed TWO per barrier
// window (32 barriers instead of 64). Slots written at iteration p
// ((2p+3)%5, (2p+4)%5) were consumed at p-1, behind the barrier: hazard-free.
// 4 warps (2x2), 64x64 warp tiles, fragments double-buffered (R12).
// ---------------------------------------------------------------------------
#define BM 128
#define BN 128
#define BK 16
#define RS 20                      // padded row stride (floats)
#define STAGES 5
#define TILE_FLOATS (BM * RS)      // 2560 per operand per stage
#define GSMEM (STAGES * 2 * TILE_FLOATS * 4)   // 102400 bytes
#define GTHREADS 128

__global__ __launch_bounds__(GTHREADS, 2)
void gemm_tf32_kernel(const float* __restrict__ A,
                      const float* __restrict__ Bt0, const float* __restrict__ Bt1,
                      const float* __restrict__ Bt2,
                      const float* __restrict__ b0, const float* __restrict__ b1,
                      const float* __restrict__ b2,
                      float* __restrict__ C0, float* __restrict__ C1,
                      float* __restrict__ C2)
{
    extern __shared__ float smf[];   // [As stages | Bs stages]
    const uint32_t sbase = smem_u32(smf);
    const uint32_t breg  = (uint32_t)(STAGES * TILE_FLOATS) * 4;

    const int z = blockIdx.z;
    const float* __restrict__ Bt   = (z == 0) ? Bt0 : (z == 1) ? Bt1 : Bt2;
    const float* __restrict__ bias = (z == 0) ? b0 : (z == 1) ? b1 : b2;
    float*       __restrict__ C    = (z == 0) ? C0 : (z == 1) ? C1 : C2;

    const int tid  = threadIdx.x;
    const int wid  = tid >> 5;
    const int lane = tid & 31;
    const int wm   = wid >> 1;        // 0..1 -> M offset 64*wm
    const int wn   = wid & 1;         // 0..1 -> N offset 64*wn
    const int lg   = lane >> 2;       // 0..7
    const int lr   = lane & 3;        // 0..3

    const int m0 = blockIdx.y * BM;
    const int n0 = blockIdx.x * BN;

    float acc[4][8][4];
#pragma unroll
    for (int i = 0; i < 4; i++)
#pragma unroll
        for (int j = 0; j < 8; j++)
#pragma unroll
            for (int q = 0; q < 4; q++) acc[i][j][q] = 0.f;

    const int sel = lane >> 3;
    const int lr8 = lane & 7;
    uint32_t aoff[4];
#pragma unroll
    for (int i = 0; i < 4; i++) {
        int row = wm * 64 + i * 16 + ((sel & 1) ? 8 : 0) + lr8;
        int col = (sel >> 1) * 4;
        aoff[i] = (uint32_t)(row * RS + col) * 4;
    }
    uint32_t boff[4];
#pragma unroll
    for (int jp = 0; jp < 4; jp++) {
        int row = wn * 64 + jp * 16 + ((sel >> 1) ? 8 : 0) + lr8;
        int col = (sel & 1) * 4;
        boff[jp] = breg + (uint32_t)(row * RS + col) * 4;
    }

    const int grow0 = tid >> 2;            // rows 0..31 (then +32,+64,+96)
    const int gk    = (tid & 3) << 2;      // k offset 0,4,8,12
    const uint32_t dstA0 = sbase + (uint32_t)(grow0 * RS + gk) * 4;
    const uint32_t dstB0 = sbase + breg + (uint32_t)(grow0 * RS + gk) * 4;
    const uint32_t rowstep = (uint32_t)(32 * RS) * 4;   // +32 rows

    auto load_stage = [&](int s, int k0) {
        const uint32_t soff = (uint32_t)(s * TILE_FLOATS) * 4;
        const float* Ap = A  + (size_t)(m0 + grow0) * HID + k0 + gk;
        const float* Bp = Bt + (size_t)(n0 + grow0) * HID + k0 + gk;
#pragma unroll
        for (int r = 0; r < 4; r++)
            cp_async16(dstA0 + soff + r * rowstep, Ap + (size_t)(r * 32) * HID);
#pragma unroll
        for (int r = 0; r < 4; r++)
            cp_async16(dstB0 + soff + r * rowstep, Bp + (size_t)(r * 32) * HID);
        CP_COMMIT();
    };

    // register fragment buffers for the two k8 blocks of one k-tile
    uint32_t afb[2][4][4], bfb[2][8][2];

    auto load_frags = [&](int buf, uint32_t kb) {
#pragma unroll
        for (int i = 0; i < 4; i++)
            ldsm_x4(afb[buf][i][0], afb[buf][i][1],
                    afb[buf][i][2], afb[buf][i][3], kb + aoff[i]);
#pragma unroll
        for (int jp = 0; jp < 4; jp++)
            ldsm_x4(bfb[buf][jp * 2][0], bfb[buf][jp * 2][1],
                    bfb[buf][jp * 2 + 1][0], bfb[buf][jp * 2 + 1][1],
                    kb + boff[jp]);
    };
    auto mma_all = [&](int buf) {
#pragma unroll
        for (int i = 0; i < 4; i++)
#pragma unroll
            for (int j = 0; j < 8; j++)
                mma_tf32(acc[i][j],
                         afb[buf][i][0], afb[buf][i][1],
                         afb[buf][i][2], afb[buf][i][3],
                         bfb[buf][j][0], bfb[buf][j][1]);
    };

    // prologue: k-tiles 0,1,2 into slots 0,1,2
#pragma unroll
    for (int s = 0; s < 3; s++) load_stage(s, s * BK);

    const int KIT = HID / BK;   // 64 k-tiles
    const int PIT = KIT / 2;    // 32 barrier windows

#pragma unroll 1
    for (int p = 0; p < PIT; p++) {
        // newest committed k-tile is min(2p+2, KIT-1); wait so that both
        // k-tiles consumed this window (2p, 2p+1) are complete.
        if (2 * p + 2 >= KIT) { CP_WAIT(0); } else { CP_WAIT(1); }
        __syncthreads();

        // ---- k-tile 2p ----
        {
            const uint32_t soff =
                sbase + (uint32_t)(((2 * p) % STAGES) * TILE_FLOATS) * 4;
            load_frags(0, soff);
            load_frags(1, soff + 32);
            mma_all(0);
            const int kt = 2 * p + 3;
            if (kt < KIT) load_stage(kt % STAGES, kt * BK);
            mma_all(1);
        }
        // ---- k-tile 2p+1 ----
        {
            const uint32_t soff =
                sbase + (uint32_t)(((2 * p + 1) % STAGES) * TILE_FLOATS) * 4;
            load_frags(0, soff);
            load_frags(1, soff + 32);
            mma_all(0);
            const int kt = 2 * p + 4;
            if (kt < KIT) load_stage(kt % STAGES, kt * BK);
            mma_all(1);
        }
    }

#pragma unroll
    for (int i = 0; i < 4; i++) {
        const int row = m0 + wm * 64 + i * 16 + lg;
#pragma unroll
        for (int j = 0; j < 8; j++) {
            const int col = n0 + wn * 64 + j * 8 + lr * 2;
            const float bx = bias[col], by = bias[col + 1];
            float2 v0 = make_float2(acc[i][j][0] + bx, acc[i][j][1] + by);
            float2 v1 = make_float2(acc[i][j][2] + bx, acc[i][j][3] + by);
            *reinterpret_cast<float2*>(&C[(size_t)row * HID + col])       = v0;
            *reinterpret_cast<float2*>(&C[(size_t)(row + 8) * HID + col]) = v1;
        }
    }
}

// ---------------------------------------------------------------------------
// Per-token head-to-head attention: TWO tokens per 256-thread block.
// R13: packed f32x2 math + split accumulators (8 independent FMA chains)
// to break the serial dependency chains that capped issue at 35%.
// ---------------------------------------------------------------------------
#define KTS 17   // skT4 row stride (float4)

__global__ __launch_bounds__(256)
void attention_kernel(const float* __restrict__ q,
                      const float* __restrict__ k,
                      const float* __restrict__ v,
                      float* __restrict__ attn)
{
    __shared__ float4 sq4[2][NHEAD * 16];     // [tok][h][d4]
    __shared__ float4 skT4[2][16 * KTS];      // [tok][d4][e]
    __shared__ float4 sv4[2][NHEAD * 16];     // [tok][e][d4]

    const int t  = threadIdx.x;
    const int hi = t >> 4;      // head
    const int lo = t & 15;      // score: e, output: d4
    const size_t b0 = (size_t)(blockIdx.x * 2) * (HID / 4);
    const size_t b1 = b0 + (HID / 4);

    const float4* q4 = reinterpret_cast<const float4*>(q);
    const float4* k4 = reinterpret_cast<const float4*>(k);
    const float4* v4 = reinterpret_cast<const float4*>(v);

    float4 q0 = q4[b0 + t], k0 = k4[b0 + t], v0 = v4[b0 + t];
    float4 q1 = q4[b1 + t], k1 = k4[b1 + t], v1 = v4[b1 + t];

    sq4[0][t]              = q0;
    skT4[0][lo * KTS + hi] = k0;
    sv4[0][t]              = v0;
    sq4[1][t]              = q1;
    skT4[1][lo * KTS + hi] = k1;
    sv4[1][t]              = v1;
    __syncthreads();

    const int lanebase = t & 16;
#pragma unroll
    for (int tok = 0; tok < 2; tok++) {
        // scores: thread (h=hi, e=lo); two packed accumulators = 4 chains
        unsigned long long sa = 0ull, sb = 0ull;
#pragma unroll
        for (int i = 0; i < 16; i += 2) {
            float4 a0 = sq4[tok][hi * 16 + i];
            float4 bq0 = skT4[tok][i * KTS + lo];
            float4 a1 = sq4[tok][hi * 16 + i + 1];
            float4 bq1 = skT4[tok][(i + 1) * KTS + lo];
            sa = fma2(pack2(a0.x, a0.y), pack2(bq0.x, bq0.y), sa);
            sb = fma2(pack2(a1.x, a1.y), pack2(bq1.x, bq1.y), sb);
            sa = fma2(pack2(a0.z, a0.w), pack2(bq0.z, bq0.w), sa);
            sb = fma2(pack2(a1.z, a1.w), pack2(bq1.z, bq1.w), sb);
        }
        float s0, s1, s2, s3;
        unpack2(sa, s0, s1);
        unpack2(sb, s2, s3);
        float s = ((s0 + s1) + (s2 + s3)) * 0.125f;   // 1/sqrt(64)

        // softmax across the 16-lane group (same h), in registers
        float mx = s;
#pragma unroll
        for (int off = 8; off >= 1; off >>= 1)
            mx = fmaxf(mx, __shfl_xor_sync(0xffffffffu, mx, off));
        float p = __expf(s - mx);
        float sum = p;
#pragma unroll
        for (int off = 8; off >= 1; off >>= 1)
            sum += __shfl_xor_sync(0xffffffffu, sum, off);
        p *= (1.f / sum);

        // output: thread (h=hi, d4=lo); packed accumulation (2 chains)
        unsigned long long o01 = 0ull, o23 = 0ull;
#pragma unroll
        for (int e = 0; e < NHEAD; e++) {
            float  pe = __shfl_sync(0xffffffffu, p, lanebase | e, 32);
            unsigned long long pp = pack2(pe, pe);
            float4 vv = sv4[tok][e * 16 + lo];
            o01 = fma2(pp, pack2(vv.x, vv.y), o01);
            o23 = fma2(pp, pack2(vv.z, vv.w), o23);
        }
        float4 o;
        unpack2(o01, o.x, o.y);
        unpack2(o23, o.z, o.w);
        o.x = to_tf32(o.x); o.y = to_tf32(o.y);
        o.z = to_tf32(o.z); o.w = to_tf32(o.w);
        reinterpret_cast<float4*>(attn)[(tok == 0 ? b0 : b1) + t] = o;
    }
}

// ---------------------------------------------------------------------------
// Launch
// ---------------------------------------------------------------------------
extern "C" void kernel_launch(void* const* d_in, const int* in_sizes, int n_in,
                              void* d_out, int out_size)
{
    const float* x  = (const float*)d_in[0];
    const float* Wq = (const float*)d_in[1];
    const float* bq = (const float*)d_in[2];
    const float* Wk = (const float*)d_in[3];
    const float* bk = (const float*)d_in[4];
    const float* Wv = (const float*)d_in[5];
    const float* bv = (const float*)d_in[6];
    const float* Wo = (const float*)d_in[7];
    const float* bo = (const float*)d_in[8];
    float* out = (float*)d_out;

    float *xa, *wt, *qp, *kp, *vp, *ap;
    cudaGetSymbolAddress((void**)&xa, g_xa);
    cudaGetSymbolAddress((void**)&wt, g_wt);
    cudaGetSymbolAddress((void**)&qp, g_q);
    cudaGetSymbolAddress((void**)&kp, g_k);
    cudaGetSymbolAddress((void**)&vp, g_v);
    cudaGetSymbolAddress((void**)&ap, g_attn);

    static bool attr_set = false;
    if (!attr_set) {
        cudaFuncSetAttribute(gemm_tf32_kernel,
                             cudaFuncAttributeMaxDynamicSharedMemorySize, GSMEM);
        attr_set = true;
    }

    // 0) staging (one launch): tf32-round x; transpose+round the four W's
    staging_kernel<<<NCONV + NTRAN, 256>>>(x, xa, Wq, Wk, Wv, Wo, wt);

    // 1) fused QKV projections
    dim3 gridQKV(HID / BN, MTOT / BM, 3);
    gemm_tf32_kernel<<<gridQKV, GTHREADS, GSMEM>>>(
        xa, wt + 0 * (size_t)HID * HID, wt + 1 * (size_t)HID * HID,
        wt + 2 * (size_t)HID * HID, bq, bk, bv, qp, kp, vp);

    // 2) per-token attention (2 tokens per block)
    attention_kernel<<<MTOT / 2, 256>>>(qp, kp, vp, ap);

    // 3) output projection
    dim3 gridO(HID / BN, MTOT / BM, 1);
    gemm_tf32_kernel<<<gridO, GTHREADS, GSMEM>>>(
        ap, wt + 3 * (size_t)HID * HID, wt + 3 * (size_t)HID * HID,
        wt + 3 * (size_t)HID * HID, bo, bo, bo, out, out, out);
}